// round 1
// baseline (speedup 1.0000x reference)
#include <cuda_runtime.h>
#include <math.h>

// Problem constants
#define Bn 4
#define Tn 200
#define Un 100
#define Dn 512
#define Vn 2048
#define EROWS (Bn * Tn)   // 800
#define PROWS (Bn * Un)   // 400
#define TUn   (Tn * Un)   // 20000
#define M_TOTAL (Bn * Tn * Un)  // 80000

#define PAD 68            // smem row stride (floats): 68*4=272B, 16B-aligned rows

// Scratch for projected e [800,512] and p [400,512]
__device__ float g_e[EROWS * Dn];
__device__ float g_p[PROWS * Dn];

#define FMA16(ACC, AV, BV)                                        \
    ACC[0][0] += AV.x * BV.x; ACC[0][1] += AV.x * BV.y;           \
    ACC[0][2] += AV.x * BV.z; ACC[0][3] += AV.x * BV.w;           \
    ACC[1][0] += AV.y * BV.x; ACC[1][1] += AV.y * BV.y;           \
    ACC[1][2] += AV.y * BV.z; ACC[1][3] += AV.y * BV.w;           \
    ACC[2][0] += AV.z * BV.x; ACC[2][1] += AV.z * BV.y;           \
    ACC[2][2] += AV.z * BV.z; ACC[2][3] += AV.z * BV.w;           \
    ACC[3][0] += AV.w * BV.x; ACC[3][1] += AV.w * BV.y;           \
    ACC[3][2] += AV.w * BV.z; ACC[3][3] += AV.w * BV.w;

// ---------------------------------------------------------------------------
// Projection: out[r][d] = sum_k X[r][k] * W[d][k] + bias[d]
// X: [rows, 512], W: [512, 512] (d-major rows), out: [rows, 512]
// BM=64, BN=64, BK=32, 256 threads, 4x4 micro-tile.
// ---------------------------------------------------------------------------
__global__ __launch_bounds__(256)
void proj_kernel(const float* __restrict__ X, const float* __restrict__ W,
                 const float* __restrict__ bias, float* __restrict__ out,
                 int rows)
{
    __shared__ float Xs[32][PAD];   // [k][r]
    __shared__ float Ws[32][PAD];   // [k][d]
    const int tid  = threadIdx.x;
    const int row0 = blockIdx.x * 64;
    const int col0 = blockIdx.y * 64;
    const int tx = tid & 15;
    const int ty = tid >> 4;

    float acc[4][4] = {};

    for (int k0 = 0; k0 < Dn; k0 += 32) {
        __syncthreads();
#pragma unroll
        for (int i = 0; i < 8; i++) {
            int idx = tid + i * 256;      // 2048 elems = 64 r x 32 k
            int k = idx & 31;
            int r = idx >> 5;
            int row = row0 + r;
            Xs[k][r] = (row < rows) ? X[row * Dn + k0 + k] : 0.0f;
            Ws[k][r] = W[(col0 + r) * Dn + k0 + k];
        }
        __syncthreads();
#pragma unroll
        for (int k = 0; k < 32; k++) {
            float4 av = *(const float4*)&Xs[k][ty * 4];
            float4 bv = *(const float4*)&Ws[k][tx * 4];
            FMA16(acc, av, bv);
        }
    }

    float4 bs = *(const float4*)&bias[col0 + tx * 4];
#pragma unroll
    for (int i = 0; i < 4; i++) {
        int row = row0 + ty * 4 + i;
        if (row < rows) {
            float4 o;
            o.x = acc[i][0] + bs.x;
            o.y = acc[i][1] + bs.y;
            o.z = acc[i][2] + bs.z;
            o.w = acc[i][3] + bs.w;
            *(float4*)&out[row * Dn + col0 + tx * 4] = o;
        }
    }
}

// ---------------------------------------------------------------------------
// Fused joint: per CTA, 64 rows m = (b,t,u). Compute A = tanh(e_row + p_row)
// ONCE into SMEM as [k][r] (fp32), then loop v over 2048 in 64-wide tiles,
// streaming out_w K-chunks through a double-buffered SMEM tile.
// out[m][v] = sum_k A[k][m] * out_w[v][k] + out_b[v]
// ---------------------------------------------------------------------------
#define JOINT_SMEM_FLOATS (Dn * PAD + 2 * 32 * PAD)
#define JOINT_SMEM_BYTES  (JOINT_SMEM_FLOATS * 4)

__global__ __launch_bounds__(256)
void joint_kernel(const float* __restrict__ ow, const float* __restrict__ ob,
                  float* __restrict__ out)
{
    extern __shared__ float sm[];
    float* As = sm;                 // [512][PAD] : [k][r]
    float* Bs = sm + Dn * PAD;      // [2][32][PAD] : [buf][k][v]

    const int tid = threadIdx.x;
    const int m0  = blockIdx.x * 64;

    // ---- Phase 1: tanh(e + p) into As, computed exactly once ----
    {
        int r  = tid & 63;          // row within tile
        int kb = tid >> 6;          // 0..3 -> k range [kb*128, kb*128+128)
        int m  = m0 + r;
        int b  = m / TUn;
        int rem = m - b * TUn;
        int t  = rem / Un;
        int u  = rem - t * Un;
        const float* er = g_e + (b * Tn + t) * Dn;
        const float* pr = g_p + (b * Un + u) * Dn;
#pragma unroll 4
        for (int k = kb * 128; k < kb * 128 + 128; k++) {
            As[k * PAD + r] = tanhf(er[k] + pr[k]);
        }
    }
    __syncthreads();

    const int tx = tid & 15;        // v micro (4 cols)
    const int ty = tid >> 4;        // m micro (4 rows)
    const int v_thr = tid >> 3;     // 0..31 : v row within B chunk
    const int kq    = tid & 7;      // 0..7  : float4 index within 32-k chunk

    for (int v0 = 0; v0 < Vn; v0 += 64) {
        float acc[4][4] = {};
        float4 nx0, nx1;

        // Prologue: load B chunk 0 into buf 0
        {
            const float* src = ow + (size_t)(v0 + v_thr) * Dn + kq * 4;
            nx0 = *(const float4*)src;
            nx1 = *(const float4*)(src + 32 * Dn);
            float* d0 = Bs + (kq * 4) * PAD + v_thr;
            d0[0 * PAD] = nx0.x; d0[1 * PAD] = nx0.y;
            d0[2 * PAD] = nx0.z; d0[3 * PAD] = nx0.w;
            float* d1 = d0 + 32;
            d1[0 * PAD] = nx1.x; d1[1 * PAD] = nx1.y;
            d1[2 * PAD] = nx1.z; d1[3 * PAD] = nx1.w;
        }
        __syncthreads();

        for (int kb = 0; kb < 16; kb++) {
            int buf = kb & 1;
            if (kb < 15) {
                const float* src = ow + (size_t)(v0 + v_thr) * Dn
                                      + (kb + 1) * 32 + kq * 4;
                nx0 = *(const float4*)src;
                nx1 = *(const float4*)(src + 32 * Dn);
            }
            const float* Ab = As + kb * 32 * PAD;
            const float* Bb = Bs + buf * (32 * PAD);
#pragma unroll
            for (int kk = 0; kk < 32; kk++) {
                float4 av = *(const float4*)(Ab + kk * PAD + ty * 4);
                float4 bv = *(const float4*)(Bb + kk * PAD + tx * 4);
                FMA16(acc, av, bv);
            }
            if (kb < 15) {
                float* d0 = Bs + (buf ^ 1) * (32 * PAD) + (kq * 4) * PAD + v_thr;
                d0[0 * PAD] = nx0.x; d0[1 * PAD] = nx0.y;
                d0[2 * PAD] = nx0.z; d0[3 * PAD] = nx0.w;
                float* d1 = d0 + 32;
                d1[0 * PAD] = nx1.x; d1[1 * PAD] = nx1.y;
                d1[2 * PAD] = nx1.z; d1[3 * PAD] = nx1.w;
            }
            __syncthreads();
        }

        // Epilogue: add bias, store 4x4 micro-tile (float4 stores)
        float4 bias = *(const float4*)&ob[v0 + tx * 4];
#pragma unroll
        for (int i = 0; i < 4; i++) {
            int m = m0 + ty * 4 + i;
            float4 o;
            o.x = acc[i][0] + bias.x;
            o.y = acc[i][1] + bias.y;
            o.z = acc[i][2] + bias.z;
            o.w = acc[i][3] + bias.w;
            *(float4*)&out[(size_t)m * Vn + v0 + tx * 4] = o;
        }
    }
}

// ---------------------------------------------------------------------------
extern "C" void kernel_launch(void* const* d_in, const int* in_sizes, int n_in,
                              void* d_out, int out_size)
{
    const float* enc_out  = (const float*)d_in[0];
    const float* pred_out = (const float*)d_in[1];
    const float* enc_w    = (const float*)d_in[2];
    const float* enc_b    = (const float*)d_in[3];
    const float* pred_w   = (const float*)d_in[4];
    const float* pred_b   = (const float*)d_in[5];
    const float* out_w    = (const float*)d_in[6];
    const float* out_b    = (const float*)d_in[7];
    float* out = (float*)d_out;

    float *ge = nullptr, *gp = nullptr;
    cudaGetSymbolAddress((void**)&ge, g_e);
    cudaGetSymbolAddress((void**)&gp, g_p);

    // Projections: e = enc_out @ enc_w^T + enc_b ; p = pred_out @ pred_w^T + pred_b
    proj_kernel<<<dim3((EROWS + 63) / 64, Dn / 64), 256>>>(enc_out, enc_w, enc_b, ge, EROWS);
    proj_kernel<<<dim3((PROWS + 63) / 64, Dn / 64), 256>>>(pred_out, pred_w, pred_b, gp, PROWS);

    // Fused tanh + vocab GEMM
    cudaFuncSetAttribute(joint_kernel,
                         cudaFuncAttributeMaxDynamicSharedMemorySize,
                         JOINT_SMEM_BYTES);
    joint_kernel<<<M_TOTAL / 64, 256, JOINT_SMEM_BYTES>>>(out_w, out_b, out);
}

// round 3
// speedup vs baseline: 9.0164x; 9.0164x over previous
#include <cuda_runtime.h>
#include <cuda_fp16.h>
#include <cstdint>
#include <math.h>

// ---------------- problem constants ----------------
#define Bn 4
#define Tn 200
#define Un 100
#define Dn 512
#define Vn 2048
#define EROWS (Bn * Tn)          // 800
#define PROWS (Bn * Un)          // 400
#define TUn   (Tn * Un)          // 20000
#define M_TOTAL (Bn * Tn * Un)   // 80000

#define M_TILE 128
#define N_TILE 128
#define KC     64
#define NKC    (Dn / KC)         // 8
#define NV     (Vn / N_TILE)     // 16

#define PAD 68

// A tile: fp16 [128 m][512 k], row stride 1040 B (1024 + 16 pad -> conflict-free ldmatrix)
#define ASTR 1040
#define A_BYTES (M_TILE * ASTR)            // 133120
// B tile: fp16 [128 n][64 k], row stride 144 B, double buffered
#define BSTR 144
#define BBUF (N_TILE * BSTR)               // 18432
#define JOINT_SMEM (A_BYTES + 2 * BBUF)    // 169984

// ---------------- global scratch ----------------
__device__ float g_e[EROWS * Dn];
__device__ float g_p[PROWS * Dn];
__device__ __half g_wh[Vn * Dn];

// ---------------- helpers ----------------
__device__ __forceinline__ uint32_t smem_to_u32(const void* p) {
    uint32_t a;
    asm("{ .reg .u64 t; cvta.to.shared.u64 t, %1; cvt.u32.u64 %0, t; }"
        : "=r"(a) : "l"(p));
    return a;
}

#define LDSM4(R, addr) \
    asm volatile("ldmatrix.sync.aligned.m8n8.x4.shared.b16 {%0,%1,%2,%3}, [%4];" \
        : "=r"((R)[0]), "=r"((R)[1]), "=r"((R)[2]), "=r"((R)[3]) : "r"(addr))

#define MMA16816(C, A, B0, B1) \
    asm volatile("mma.sync.aligned.m16n8k16.row.col.f32.f16.f16.f32 " \
        "{%0,%1,%2,%3}, {%4,%5,%6,%7}, {%8,%9}, {%0,%1,%2,%3};" \
        : "+f"((C)[0]), "+f"((C)[1]), "+f"((C)[2]), "+f"((C)[3]) \
        : "r"((A)[0]), "r"((A)[1]), "r"((A)[2]), "r"((A)[3]), "r"(B0), "r"(B1))

#define CP_ASYNC16(dst, src) \
    asm volatile("cp.async.cg.shared.global [%0], [%1], 16;" \
        :: "r"(dst), "l"(src) : "memory")
#define CP_COMMIT() asm volatile("cp.async.commit_group;" ::: "memory")
#define CP_WAIT1()  asm volatile("cp.async.wait_group 1;" ::: "memory")
#define CP_WAIT0()  asm volatile("cp.async.wait_group 0;" ::: "memory")

// ---------------------------------------------------------------------------
// Projection (known-correct): out[r][d] = X[r]·W[d] + bias[d]
// ---------------------------------------------------------------------------
#define FMA16(ACC, AV, BV)                                        \
    ACC[0][0] += AV.x * BV.x; ACC[0][1] += AV.x * BV.y;           \
    ACC[0][2] += AV.x * BV.z; ACC[0][3] += AV.x * BV.w;           \
    ACC[1][0] += AV.y * BV.x; ACC[1][1] += AV.y * BV.y;           \
    ACC[1][2] += AV.y * BV.z; ACC[1][3] += AV.y * BV.w;           \
    ACC[2][0] += AV.z * BV.x; ACC[2][1] += AV.z * BV.y;           \
    ACC[2][2] += AV.z * BV.z; ACC[2][3] += AV.z * BV.w;           \
    ACC[3][0] += AV.w * BV.x; ACC[3][1] += AV.w * BV.y;           \
    ACC[3][2] += AV.w * BV.z; ACC[3][3] += AV.w * BV.w;

__global__ __launch_bounds__(256)
void proj_kernel(const float* __restrict__ X, const float* __restrict__ W,
                 const float* __restrict__ bias, float* __restrict__ out,
                 int rows)
{
    __shared__ float Xs[32][PAD];
    __shared__ float Ws[32][PAD];
    const int tid  = threadIdx.x;
    const int row0 = blockIdx.x * 64;
    const int col0 = blockIdx.y * 64;
    const int tx = tid & 15;
    const int ty = tid >> 4;

    float acc[4][4] = {};

    for (int k0 = 0; k0 < Dn; k0 += 32) {
        __syncthreads();
#pragma unroll
        for (int i = 0; i < 8; i++) {
            int idx = tid + i * 256;
            int k = idx & 31;
            int r = idx >> 5;
            int row = row0 + r;
            Xs[k][r] = (row < rows) ? X[row * Dn + k0 + k] : 0.0f;
            Ws[k][r] = W[(col0 + r) * Dn + k0 + k];
        }
        __syncthreads();
#pragma unroll
        for (int k = 0; k < 32; k++) {
            float4 av = *(const float4*)&Xs[k][ty * 4];
            float4 bv = *(const float4*)&Ws[k][tx * 4];
            FMA16(acc, av, bv);
        }
    }

    float4 bs = *(const float4*)&bias[col0 + tx * 4];
#pragma unroll
    for (int i = 0; i < 4; i++) {
        int row = row0 + ty * 4 + i;
        if (row < rows) {
            float4 o;
            o.x = acc[i][0] + bs.x;
            o.y = acc[i][1] + bs.y;
            o.z = acc[i][2] + bs.z;
            o.w = acc[i][3] + bs.w;
            *(float4*)&out[row * Dn + col0 + tx * 4] = o;
        }
    }
}

// ---------------------------------------------------------------------------
// out_w fp32 -> fp16
// ---------------------------------------------------------------------------
__global__ __launch_bounds__(256)
void convert_w_kernel(const float* __restrict__ ow, __half* __restrict__ wh)
{
    int i = blockIdx.x * 256 + threadIdx.x;
    wh[i] = __float2half_rn(ow[i]);
}

// ---------------------------------------------------------------------------
// Joint: per CTA 128 m rows; A=tanh(e+p) fp16 in SMEM once; loop 16 v-tiles;
// B chunks (64k) double-buffered via cp.async; warp-level m16n8k16 HMMA.
// ---------------------------------------------------------------------------
__global__ __launch_bounds__(256, 1)
void joint_kernel(const __half* __restrict__ wh, const float* __restrict__ ob,
                  float* __restrict__ out)
{
    extern __shared__ char sm[];
    const uint32_t sA = smem_to_u32(sm);
    const uint32_t sB = sA + A_BYTES;

    const int tid  = threadIdx.x;
    const int lane = tid & 31;
    const int w    = tid >> 5;
    const int wm   = w & 3;          // warp m index 0..3
    const int wn   = w >> 2;         // warp n index 0..1
    const int m0w  = wm * 32;
    const int n0w  = wn * 64;
    const int m0   = blockIdx.x * M_TILE;

    // ---- Phase 1: A = tanh(e + p) -> fp16 SMEM tile ----
#pragma unroll 4
    for (int i = 0; i < 32; i++) {
        int q  = i * 256 + tid;      // 0..8191
        int r  = q >> 6;             // m row 0..127
        int kb = q & 63;             // 8-elem k block
        int m  = m0 + r;
        int b  = m / TUn;
        int rem = m - b * TUn;
        int t  = rem / Un;
        int u  = rem - t * Un;
        const float4* er = (const float4*)(g_e + (b * Tn + t) * Dn + kb * 8);
        const float4* pr = (const float4*)(g_p + (b * Un + u) * Dn + kb * 8);
        float4 e0 = er[0], p0 = pr[0];
        float4 e1 = er[1], p1 = pr[1];
        __half2 h0 = __floats2half2_rn(tanhf(e0.x + p0.x), tanhf(e0.y + p0.y));
        __half2 h1 = __floats2half2_rn(tanhf(e0.z + p0.z), tanhf(e0.w + p0.w));
        __half2 h2 = __floats2half2_rn(tanhf(e1.x + p1.x), tanhf(e1.y + p1.y));
        __half2 h3 = __floats2half2_rn(tanhf(e1.z + p1.z), tanhf(e1.w + p1.w));
        uint4 pkt;
        memcpy(&pkt.x, &h0, 4); memcpy(&pkt.y, &h1, 4);
        memcpy(&pkt.z, &h2, 4); memcpy(&pkt.w, &h3, 4);
        *(uint4*)(sm + r * ASTR + kb * 16) = pkt;
    }
    __syncthreads();

    // ldmatrix lane address components
    const uint32_t aAddrBase = sA + (m0w + (lane & 15)) * ASTR + (lane >> 4) * 16;
    const int bN   = (lane & 7) + ((lane >> 4) & 1) * 8;   // n row within 16-group
    const int bKof = ((lane >> 3) & 1) * 16;                // k-half byte offset

    for (int v = 0; v < NV; v++) {
        float acc[2][8][4] = {};

        // prefetch kc=0 into buf 0
        {
#pragma unroll
            for (int j = 0; j < 4; j++) {
                int q = tid + j * 256;
                int r = q >> 3, s = q & 7;
                uint32_t dst = sB + r * BSTR + s * 16;
                const __half* src = wh + (size_t)(v * N_TILE + r) * Dn + s * 8;
                CP_ASYNC16(dst, src);
            }
            CP_COMMIT();
        }

        for (int kc = 0; kc < NKC; kc++) {
            if (kc < NKC - 1) {
                int buf = (kc + 1) & 1;
#pragma unroll
                for (int j = 0; j < 4; j++) {
                    int q = tid + j * 256;
                    int r = q >> 3, s = q & 7;
                    uint32_t dst = sB + buf * BBUF + r * BSTR + s * 16;
                    const __half* src = wh + (size_t)(v * N_TILE + r) * Dn
                                           + (kc + 1) * KC + s * 8;
                    CP_ASYNC16(dst, src);
                }
                CP_COMMIT();
                CP_WAIT1();
            } else {
                CP_WAIT0();
            }
            __syncthreads();

            const uint32_t sBbuf = sB + (kc & 1) * BBUF;
#pragma unroll
            for (int ks = 0; ks < 4; ks++) {
                uint32_t a[2][4];
                uint32_t kByte = (uint32_t)(kc * KC + ks * 16) * 2;
                LDSM4(a[0], aAddrBase + kByte);
                LDSM4(a[1], aAddrBase + kByte + 16 * ASTR);
                uint32_t b[4][4];
#pragma unroll
                for (int j = 0; j < 4; j++) {
                    uint32_t addr = sBbuf + (uint32_t)(n0w + j * 16 + bN) * BSTR
                                  + (uint32_t)(ks * 32 + bKof);
                    LDSM4(b[j], addr);
                }
#pragma unroll
                for (int mi = 0; mi < 2; mi++) {
#pragma unroll
                    for (int ni = 0; ni < 8; ni++) {
                        uint32_t b0 = b[ni >> 1][(ni & 1) * 2];
                        uint32_t b1 = b[ni >> 1][(ni & 1) * 2 + 1];
                        MMA16816(acc[mi][ni], a[mi], b0, b1);
                    }
                }
            }
            __syncthreads();
        }

        // ---- epilogue: bias + store ----
#pragma unroll
        for (int mi = 0; mi < 2; mi++) {
            int gm = m0 + m0w + mi * 16 + (lane >> 2);
            float* orow0 = out + (size_t)gm * Vn + v * N_TILE;
            float* orow1 = orow0 + 8 * Vn;
#pragma unroll
            for (int ni = 0; ni < 8; ni++) {
                int gn = n0w + ni * 8 + 2 * (lane & 3);
                float2 bv = *(const float2*)(ob + v * N_TILE + gn);
                float2 o0, o1;
                o0.x = acc[mi][ni][0] + bv.x;
                o0.y = acc[mi][ni][1] + bv.y;
                o1.x = acc[mi][ni][2] + bv.x;
                o1.y = acc[mi][ni][3] + bv.y;
                *(float2*)(orow0 + gn) = o0;
                *(float2*)(orow1 + gn) = o1;
            }
        }
    }
}

// ---------------------------------------------------------------------------
extern "C" void kernel_launch(void* const* d_in, const int* in_sizes, int n_in,
                              void* d_out, int out_size)
{
    const float* enc_out  = (const float*)d_in[0];
    const float* pred_out = (const float*)d_in[1];
    const float* enc_w    = (const float*)d_in[2];
    const float* enc_b    = (const float*)d_in[3];
    const float* pred_w   = (const float*)d_in[4];
    const float* pred_b   = (const float*)d_in[5];
    const float* out_w    = (const float*)d_in[6];
    const float* out_b    = (const float*)d_in[7];
    float* out = (float*)d_out;

    float *ge = nullptr, *gp = nullptr;
    __half* wh = nullptr;
    cudaGetSymbolAddress((void**)&ge, g_e);
    cudaGetSymbolAddress((void**)&gp, g_p);
    cudaGetSymbolAddress((void**)&wh, g_wh);

    proj_kernel<<<dim3((EROWS + 63) / 64, Dn / 64), 256>>>(enc_out, enc_w, enc_b, ge, EROWS);
    proj_kernel<<<dim3((PROWS + 63) / 64, Dn / 64), 256>>>(pred_out, pred_w, pred_b, gp, PROWS);
    convert_w_kernel<<<(Vn * Dn) / 256, 256>>>(out_w, wh);

    cudaFuncSetAttribute(joint_kernel,
                         cudaFuncAttributeMaxDynamicSharedMemorySize, JOINT_SMEM);
    joint_kernel<<<M_TOTAL / M_TILE, 256, JOINT_SMEM>>>(wh, out_b, out);
}

// round 4
// speedup vs baseline: 10.5699x; 1.1723x over previous
#include <cuda_runtime.h>
#include <cuda_fp16.h>
#include <cstdint>
#include <math.h>

// ---------------- problem constants ----------------
#define Bn 4
#define Tn 200
#define Un 100
#define Dn 512
#define Vn 2048
#define EROWS (Bn * Tn)          // 800
#define PROWS (Bn * Un)          // 400
#define TUn   (Tn * Un)          // 20000
#define M_TOTAL (Bn * Tn * Un)   // 80000

#define M_TILE 128
#define N_TILE 128
#define KC     64
#define NKC    (Dn / KC)         // 8
#define NV     (Vn / N_TILE)     // 16
#define NCHUNK (NV * NKC)        // 128
#define JTHREADS 512

#define PAD 68

// A tile: fp16 [128 m][512 k], row stride 1040B (conflict-free ldmatrix)
#define ASTR 1040
#define A_BYTES (M_TILE * ASTR)            // 133120
// B tile: fp16 [128 n][64 k], row stride 144B, 4-slot ring
#define BSTR 144
#define BBUF (N_TILE * BSTR)               // 18432
#define JOINT_SMEM (A_BYTES + 4 * BBUF)    // 206848

// proj grid split
#define ENC_BLKS 13
#define PRED_BLKS 7
#define PROJ_BLKS (ENC_BLKS + PRED_BLKS)   // 20
#define CONV_BLKS 64                        // x64 * y8 = 512 sub-blocks

// ---------------- global scratch ----------------
__device__ float g_e[EROWS * Dn];
__device__ float g_p[PROWS * Dn];
__device__ __half g_wh[Vn * Dn];

// ---------------- helpers ----------------
__device__ __forceinline__ uint32_t smem_to_u32(const void* p) {
    uint32_t a;
    asm("{ .reg .u64 t; cvta.to.shared.u64 t, %1; cvt.u32.u64 %0, t; }"
        : "=r"(a) : "l"(p));
    return a;
}

#define LDSM4(R, addr) \
    asm volatile("ldmatrix.sync.aligned.m8n8.x4.shared.b16 {%0,%1,%2,%3}, [%4];" \
        : "=r"((R)[0]), "=r"((R)[1]), "=r"((R)[2]), "=r"((R)[3]) : "r"(addr))

#define MMA16816(C, A, B0, B1) \
    asm volatile("mma.sync.aligned.m16n8k16.row.col.f32.f16.f16.f32 " \
        "{%0,%1,%2,%3}, {%4,%5,%6,%7}, {%8,%9}, {%0,%1,%2,%3};" \
        : "+f"((C)[0]), "+f"((C)[1]), "+f"((C)[2]), "+f"((C)[3]) \
        : "r"((A)[0]), "r"((A)[1]), "r"((A)[2]), "r"((A)[3]), "r"(B0), "r"(B1))

#define CP_ASYNC16(dst, src) \
    asm volatile("cp.async.cg.shared.global [%0], [%1], 16;" \
        :: "r"(dst), "l"(src) : "memory")
#define CP_COMMIT() asm volatile("cp.async.commit_group;" ::: "memory")
#define CP_WAIT1()  asm volatile("cp.async.wait_group 1;" ::: "memory")
#define CP_WAIT0()  asm volatile("cp.async.wait_group 0;" ::: "memory")

// ---------------------------------------------------------------------------
// Fused preamble: blocks [0,13) enc proj, [13,20) pred proj, [20,84) W convert
// proj: out[r][d] = X[r]·W[d] + bias[d]   (BM=64, BN=64, BK=32, 4x4 micro)
// ---------------------------------------------------------------------------
#define FMA16(ACC, AV, BV)                                        \
    ACC[0][0] += AV.x * BV.x; ACC[0][1] += AV.x * BV.y;           \
    ACC[0][2] += AV.x * BV.z; ACC[0][3] += AV.x * BV.w;           \
    ACC[1][0] += AV.y * BV.x; ACC[1][1] += AV.y * BV.y;           \
    ACC[1][2] += AV.y * BV.z; ACC[1][3] += AV.y * BV.w;           \
    ACC[2][0] += AV.z * BV.x; ACC[2][1] += AV.z * BV.y;           \
    ACC[2][2] += AV.z * BV.z; ACC[2][3] += AV.z * BV.w;           \
    ACC[3][0] += AV.w * BV.x; ACC[3][1] += AV.w * BV.y;           \
    ACC[3][2] += AV.w * BV.z; ACC[3][3] += AV.w * BV.w;

__global__ __launch_bounds__(256)
void preamble_kernel(const float* __restrict__ enc_out, const float* __restrict__ enc_w,
                     const float* __restrict__ enc_b,
                     const float* __restrict__ pred_out, const float* __restrict__ pred_w,
                     const float* __restrict__ pred_b,
                     const float* __restrict__ out_w,
                     float* __restrict__ ge, float* __restrict__ gp,
                     __half* __restrict__ wh)
{
    const int bx = blockIdx.x;
    const int tid = threadIdx.x;

    if (bx >= PROJ_BLKS) {
        // ---- out_w fp32 -> fp16 convert: 512 sub-blocks x 2048 elems ----
        int idx = (bx - PROJ_BLKS) * 8 + blockIdx.y;      // 0..511
        const float4* src = (const float4*)(out_w + (size_t)idx * 2048) + tid * 2;
        float4 f0 = src[0];
        float4 f1 = src[1];
        __half2 h0 = __floats2half2_rn(f0.x, f0.y);
        __half2 h1 = __floats2half2_rn(f0.z, f0.w);
        __half2 h2 = __floats2half2_rn(f1.x, f1.y);
        __half2 h3 = __floats2half2_rn(f1.z, f1.w);
        uint4 pkt;
        memcpy(&pkt.x, &h0, 4); memcpy(&pkt.y, &h1, 4);
        memcpy(&pkt.z, &h2, 4); memcpy(&pkt.w, &h3, 4);
        *((uint4*)(wh + (size_t)idx * 2048) + tid) = pkt;
        return;
    }

    // ---- projection ----
    const float* X;  const float* W;  const float* bias;  float* out;
    int rows, row0;
    if (bx < ENC_BLKS) { X = enc_out; W = enc_w;  bias = enc_b;  out = ge; rows = EROWS; row0 = bx * 64; }
    else               { X = pred_out; W = pred_w; bias = pred_b; out = gp; rows = PROWS; row0 = (bx - ENC_BLKS) * 64; }

    __shared__ float Xs[32][PAD];
    __shared__ float Ws[32][PAD];
    const int col0 = blockIdx.y * 64;
    const int tx = tid & 15;
    const int ty = tid >> 4;

    float acc[4][4] = {};

    for (int k0 = 0; k0 < Dn; k0 += 32) {
        __syncthreads();
#pragma unroll
        for (int i = 0; i < 8; i++) {
            int idx = tid + i * 256;
            int k = idx & 31;
            int r = idx >> 5;
            int row = row0 + r;
            Xs[k][r] = (row < rows) ? X[row * Dn + k0 + k] : 0.0f;
            Ws[k][r] = W[(col0 + r) * Dn + k0 + k];
        }
        __syncthreads();
#pragma unroll
        for (int k = 0; k < 32; k++) {
            float4 av = *(const float4*)&Xs[k][ty * 4];
            float4 bv = *(const float4*)&Ws[k][tx * 4];
            FMA16(acc, av, bv);
        }
    }

    float4 bs = *(const float4*)&bias[col0 + tx * 4];
#pragma unroll
    for (int i = 0; i < 4; i++) {
        int row = row0 + ty * 4 + i;
        if (row < rows) {
            float4 o;
            o.x = acc[i][0] + bs.x;
            o.y = acc[i][1] + bs.y;
            o.z = acc[i][2] + bs.z;
            o.w = acc[i][3] + bs.w;
            *(float4*)&out[row * Dn + col0 + tx * 4] = o;
        }
    }
}

// ---------------------------------------------------------------------------
// Joint: 512 threads, 16 warps (4m x 4n), warp tile 32x32.
// A=tanh(e+p) fp16 in SMEM once. Flat 128-chunk loop (v x kc), 4-slot cp.async
// ring, ONE __syncthreads per chunk.
// ---------------------------------------------------------------------------
__global__ __launch_bounds__(JTHREADS, 1)
void joint_kernel(const __half* __restrict__ wh, const float* __restrict__ ob,
                  float* __restrict__ out)
{
    extern __shared__ char sm[];
    const uint32_t sA = smem_to_u32(sm);
    const uint32_t sB = sA + A_BYTES;

    const int tid  = threadIdx.x;
    const int lane = tid & 31;
    const int w    = tid >> 5;
    const int wm   = w & 3;          // warp m index 0..3
    const int wn   = w >> 2;         // warp n index 0..3
    const int m0w  = wm * 32;
    const int n0w  = wn * 32;
    const int m0   = blockIdx.x * M_TILE;

    // ---- Phase 1: A = tanh(e + p) -> fp16 SMEM tile ----
#pragma unroll 4
    for (int i = 0; i < 16; i++) {
        int q  = i * JTHREADS + tid; // 0..8191
        int r  = q >> 6;             // m row 0..127
        int kb = q & 63;             // 8-elem k block
        int m  = m0 + r;
        int b  = m / TUn;
        int rem = m - b * TUn;
        int t  = rem / Un;
        int u  = rem - t * Un;
        const float4* er = (const float4*)(g_e + (b * Tn + t) * Dn + kb * 8);
        const float4* pr = (const float4*)(g_p + (b * Un + u) * Dn + kb * 8);
        float4 e0 = er[0], p0 = pr[0];
        float4 e1 = er[1], p1 = pr[1];
        __half2 h0 = __floats2half2_rn(tanhf(e0.x + p0.x), tanhf(e0.y + p0.y));
        __half2 h1 = __floats2half2_rn(tanhf(e0.z + p0.z), tanhf(e0.w + p0.w));
        __half2 h2 = __floats2half2_rn(tanhf(e1.x + p1.x), tanhf(e1.y + p1.y));
        __half2 h3 = __floats2half2_rn(tanhf(e1.z + p1.z), tanhf(e1.w + p1.w));
        uint4 pkt;
        memcpy(&pkt.x, &h0, 4); memcpy(&pkt.y, &h1, 4);
        memcpy(&pkt.z, &h2, 4); memcpy(&pkt.w, &h3, 4);
        *(uint4*)(sm + r * ASTR + kb * 16) = pkt;
    }

    // ldmatrix lane address components
    const uint32_t aAddrBase = sA + (m0w + (lane & 15)) * ASTR + (lane >> 4) * 16;
    const int bN   = (lane & 7) + ((lane >> 4) & 1) * 8;
    const int bKof = ((lane >> 3) & 1) * 16;
    // cp.async per-thread coords (2 x 16B per chunk)
    const int cr0 = tid >> 3;            // row 0..63
    const int cs  = tid & 7;             // 16B slot within 64-k row

    float acc[2][4][4] = {};

    // prologue: prefetch chunk 0 into slot 0
    {
        const __half* src = wh + (size_t)cr0 * Dn + cs * 8;
#pragma unroll
        for (int j = 0; j < 2; j++) {
            CP_ASYNC16(sB + (cr0 + j * 64) * BSTR + cs * 16, src + (size_t)j * 64 * Dn);
        }
        CP_COMMIT();
    }

    for (int c = 0; c < NCHUNK; c++) {
        const int v  = c >> 3;
        const int kc = c & 7;

        if (c + 1 < NCHUNK) {
            const int vn_ = (c + 1) >> 3;
            const int kn_ = (c + 1) & 7;
            const uint32_t dst = sB + ((c + 1) & 3) * BBUF;
            const __half* src = wh + (size_t)(vn_ * N_TILE + cr0) * Dn + kn_ * KC + cs * 8;
#pragma unroll
            for (int j = 0; j < 2; j++) {
                CP_ASYNC16(dst + (cr0 + j * 64) * BSTR + cs * 16, src + (size_t)j * 64 * Dn);
            }
            CP_COMMIT();
            CP_WAIT1();
        } else {
            CP_WAIT0();
        }
        __syncthreads();

        const uint32_t sBbuf = sB + (c & 3) * BBUF;
#pragma unroll
        for (int ks = 0; ks < 4; ks++) {
            uint32_t a[2][4];
            uint32_t kByte = (uint32_t)(kc * KC + ks * 16) * 2;
            LDSM4(a[0], aAddrBase + kByte);
            LDSM4(a[1], aAddrBase + kByte + 16 * ASTR);
            uint32_t bf[2][4];
#pragma unroll
            for (int j = 0; j < 2; j++) {
                uint32_t addr = sBbuf + (uint32_t)(n0w + j * 16 + bN) * BSTR
                              + (uint32_t)(ks * 32 + bKof);
                LDSM4(bf[j], addr);
            }
#pragma unroll
            for (int mi = 0; mi < 2; mi++) {
#pragma unroll
                for (int ni = 0; ni < 4; ni++) {
                    uint32_t b0 = bf[ni >> 1][(ni & 1) * 2];
                    uint32_t b1 = bf[ni >> 1][(ni & 1) * 2 + 1];
                    MMA16816(acc[mi][ni], a[mi], b0, b1);
                }
            }
        }

        if (kc == 7) {
            // ---- epilogue for v-tile: bias + store, reset acc ----
#pragma unroll
            for (int mi = 0; mi < 2; mi++) {
                int gm = m0 + m0w + mi * 16 + (lane >> 2);
                float* orow0 = out + (size_t)gm * Vn + v * N_TILE;
                float* orow1 = orow0 + 8 * Vn;
#pragma unroll
                for (int ni = 0; ni < 4; ni++) {
                    int gn = n0w + ni * 8 + 2 * (lane & 3);
                    float2 bv = *(const float2*)(ob + v * N_TILE + gn);
                    float2 o0, o1;
                    o0.x = acc[mi][ni][0] + bv.x;
                    o0.y = acc[mi][ni][1] + bv.y;
                    o1.x = acc[mi][ni][2] + bv.x;
                    o1.y = acc[mi][ni][3] + bv.y;
                    *(float2*)(orow0 + gn) = o0;
                    *(float2*)(orow1 + gn) = o1;
#pragma unroll
                    for (int z = 0; z < 4; z++) acc[mi][ni][z] = 0.0f;
                }
            }
        }
    }
}

// ---------------------------------------------------------------------------
extern "C" void kernel_launch(void* const* d_in, const int* in_sizes, int n_in,
                              void* d_out, int out_size)
{
    const float* enc_out  = (const float*)d_in[0];
    const float* pred_out = (const float*)d_in[1];
    const float* enc_w    = (const float*)d_in[2];
    const float* enc_b    = (const float*)d_in[3];
    const float* pred_w   = (const float*)d_in[4];
    const float* pred_b   = (const float*)d_in[5];
    const float* out_w    = (const float*)d_in[6];
    const float* out_b    = (const float*)d_in[7];
    float* out = (float*)d_out;

    float *ge = nullptr, *gp = nullptr;
    __half* wh = nullptr;
    cudaGetSymbolAddress((void**)&ge, g_e);
    cudaGetSymbolAddress((void**)&gp, g_p);
    cudaGetSymbolAddress((void**)&wh, g_wh);

    preamble_kernel<<<dim3(PROJ_BLKS + CONV_BLKS, 8), 256>>>(
        enc_out, enc_w, enc_b, pred_out, pred_w, pred_b, out_w, ge, gp, wh);

    cudaFuncSetAttribute(joint_kernel,
                         cudaFuncAttributeMaxDynamicSharedMemorySize, JOINT_SMEM);
    joint_kernel<<<M_TOTAL / M_TILE, JTHREADS, JOINT_SMEM>>>(wh, out_b, out);
}